// round 7
// baseline (speedup 1.0000x reference)
#include <cuda_runtime.h>
#include <cuda_bf16.h>
#include <cstdint>

#define B_DIM 32
#define N_DIM 16384
#define D 128
#define ROWS_PER_CTA 128
#define CHUNKS_PER_B (N_DIM / ROWS_PER_CTA)   // 128
#define N_TILES (B_DIM * CHUNKS_PER_B)        // 4096
#define GEMM_CTAS 148                         // persistent: 1 CTA / SM
#define GEMM_THREADS 512
#define LDW 136                               // bf16 row stride: 16B-aligned, conflict-free ldmatrix
#define SMEM_BYTES (2 * D * LDW * 2 + D * 4)  // sW + sX (bf16) + sS (f32) = 70144

// Scratch (no allocations allowed)
__device__ float g_part[N_TILES * D];   // per-chunk partial row sums
__device__ float g_s[B_DIM * D];        // s[b] = xsum[b] @ w2 + bias

// ---------------------------------------------------------------------------
// Pass 1: deterministic partial reduction of x over the set dimension.
// ---------------------------------------------------------------------------
__global__ __launch_bounds__(256) void reduce_kernel(const float* __restrict__ x) {
    __shared__ float4 red[8][32];
    int t = threadIdx.x;
    int d4 = t & 31;
    int rg = t >> 5;
    const float4* xr = (const float4*)x + (size_t)blockIdx.x * ROWS_PER_CTA * (D / 4);
    float4 acc = {0.f, 0.f, 0.f, 0.f};
    #pragma unroll
    for (int r = rg; r < ROWS_PER_CTA; r += 8) {
        float4 v = xr[r * 32 + d4];
        acc.x += v.x; acc.y += v.y; acc.z += v.z; acc.w += v.w;
    }
    red[rg][d4] = acc;
    __syncthreads();
    if (t < 32) {
        float4 s = red[0][t];
        #pragma unroll
        for (int i = 1; i < 8; i++) {
            float4 v = red[i][t];
            s.x += v.x; s.y += v.y; s.z += v.z; s.w += v.w;
        }
        ((float4*)g_part)[blockIdx.x * 32 + t] = s;
    }
}

// ---------------------------------------------------------------------------
// Pass 2: s[b][e] = sum_d xsum[b][d] * w2[d][e] + bias[e]
// ---------------------------------------------------------------------------
__global__ __launch_bounds__(128) void svec_kernel(const float* __restrict__ w2,
                                                   const float* __restrict__ bias) {
    __shared__ float xs[D];
    int b = blockIdx.x;
    int t = threadIdx.x;
    float acc = 0.f;
    const float* p = g_part + (size_t)b * CHUNKS_PER_B * D + t;
    #pragma unroll 8
    for (int c = 0; c < CHUNKS_PER_B; c++) acc += p[c * D];
    xs[t] = acc;
    __syncthreads();
    float s = bias[t];
    #pragma unroll 8
    for (int d = 0; d < D; d++) s += xs[d] * w2[d * D + t];
    g_s[b * D + t] = s;
}

// ---------------------------------------------------------------------------
// Pass 3: persistent pipelined GEMM: out[row,:] = x[row,:] @ w1 + s[b]
// ---------------------------------------------------------------------------
__device__ __forceinline__ void ldmatrix_x4(uint32_t (&r)[4], uint32_t addr) {
    asm volatile("ldmatrix.sync.aligned.m8n8.x4.shared.b16 {%0,%1,%2,%3}, [%4];"
                 : "=r"(r[0]), "=r"(r[1]), "=r"(r[2]), "=r"(r[3]) : "r"(addr));
}
__device__ __forceinline__ void ldmatrix_x4_trans(uint32_t (&r)[4], uint32_t addr) {
    asm volatile("ldmatrix.sync.aligned.m8n8.x4.trans.shared.b16 {%0,%1,%2,%3}, [%4];"
                 : "=r"(r[0]), "=r"(r[1]), "=r"(r[2]), "=r"(r[3]) : "r"(addr));
}
__device__ __forceinline__ void mma16816(float (&c)[4], const uint32_t (&a)[4],
                                         uint32_t b0, uint32_t b1) {
    asm volatile("mma.sync.aligned.m16n8k16.row.col.f32.bf16.bf16.f32 "
                 "{%0,%1,%2,%3}, {%4,%5,%6,%7}, {%8,%9}, {%0,%1,%2,%3};"
                 : "+f"(c[0]), "+f"(c[1]), "+f"(c[2]), "+f"(c[3])
                 : "r"(a[0]), "r"(a[1]), "r"(a[2]), "r"(a[3]), "r"(b0), "r"(b1));
}

__global__ __launch_bounds__(GEMM_THREADS, 1) void gemm_kernel(const float* __restrict__ x,
                                                               const float* __restrict__ w1,
                                                               float* __restrict__ out) {
    extern __shared__ unsigned char smem_raw[];
    __nv_bfloat16* sW = (__nv_bfloat16*)smem_raw;         // [128][LDW]
    __nv_bfloat16* sX = sW + D * LDW;                     // [128][LDW]
    float* sS = (float*)(sX + D * LDW);                   // [128]

    int tid = threadIdx.x;
    int warp = tid >> 5, lane = tid & 31;
    int mwarp = warp & 7;          // which 16-row block
    int nhalf = warp >> 3;         // which 64-col half
    int m0 = mwarp * 16;
    int lrow = lane & 15;
    int lcol8 = (lane >> 4) * 8;

    // w1 fp32 -> bf16 smem, once per (persistent) CTA
    const float4* w4 = (const float4*)w1;
    #pragma unroll
    for (int j = 0; j < 8; j++) {
        int i = tid + j * GEMM_THREADS;           // 4096 float4
        int r = i >> 5, c4 = i & 31;
        float4 v = w4[i];
        *(__nv_bfloat162*)&sW[r * LDW + c4 * 4]     = __floats2bfloat162_rn(v.x, v.y);
        *(__nv_bfloat162*)&sW[r * LDW + c4 * 4 + 2] = __floats2bfloat162_rn(v.z, v.w);
    }

    // Prologue: prefetch first tile into registers (8 float4 / thread)
    float4 pf[8];
    {
        const float4* xt = (const float4*)x + (size_t)blockIdx.x * (ROWS_PER_CTA * 32);
        #pragma unroll
        for (int j = 0; j < 8; j++) pf[j] = xt[tid + j * GEMM_THREADS];
    }

    for (int tile = blockIdx.x; tile < N_TILES; tile += GEMM_CTAS) {
        int b = tile >> 7;  // 128 tiles per batch

        // Stage prefetched tile into bf16 smem
        #pragma unroll
        for (int j = 0; j < 8; j++) {
            int i = tid + j * GEMM_THREADS;
            int r = i >> 5, c4 = i & 31;
            *(__nv_bfloat162*)&sX[r * LDW + c4 * 4]     = __floats2bfloat162_rn(pf[j].x, pf[j].y);
            *(__nv_bfloat162*)&sX[r * LDW + c4 * 4 + 2] = __floats2bfloat162_rn(pf[j].z, pf[j].w);
        }
        if (tid < D) sS[tid] = g_s[b * D + tid];
        __syncthreads();

        // Kick off next tile's loads (overlaps with MMA + epilogue below)
        int nt = tile + GEMM_CTAS;
        if (nt < N_TILES) {
            const float4* xt = (const float4*)x + (size_t)nt * (ROWS_PER_CTA * 32);
            #pragma unroll
            for (int j = 0; j < 8; j++) pf[j] = xt[tid + j * GEMM_THREADS];
        }

        // Preload all A fragments: m16 x k128 per warp
        uint32_t a[8][4];
        #pragma unroll
        for (int k = 0; k < 8; k++) {
            uint32_t addr = (uint32_t)__cvta_generic_to_shared(
                &sX[(m0 + lrow) * LDW + k * 16 + lcol8]);
            ldmatrix_x4(a[k], addr);
        }

        float acc[8][4];
        #pragma unroll
        for (int i = 0; i < 8; i++) {
            acc[i][0] = 0.f; acc[i][1] = 0.f; acc[i][2] = 0.f; acc[i][3] = 0.f;
        }

        #pragma unroll
        for (int n2 = 0; n2 < 4; n2++) {
            int ncol0 = nhalf * 64 + n2 * 16;
            #pragma unroll
            for (int k = 0; k < 8; k++) {
                uint32_t bfr[4];
                uint32_t addr = (uint32_t)__cvta_generic_to_shared(
                    &sW[(k * 16 + lrow) * LDW + ncol0 + lcol8]);
                ldmatrix_x4_trans(bfr, addr);
                mma16816(acc[2 * n2],     a[k], bfr[0], bfr[1]);
                mma16816(acc[2 * n2 + 1], a[k], bfr[2], bfr[3]);
            }
        }

        // Epilogue: add s[b] broadcast, store float2 pairs
        int g = lane >> 2;
        int tc = (lane & 3) * 2;
        float* outp = out + ((size_t)tile * ROWS_PER_CTA + m0) * D;
        #pragma unroll
        for (int nb = 0; nb < 8; nb++) {
            int col = nhalf * 64 + nb * 8 + tc;
            float s0 = sS[col], s1 = sS[col + 1];
            float2 v0 = make_float2(acc[nb][0] + s0, acc[nb][1] + s1);
            float2 v1 = make_float2(acc[nb][2] + s0, acc[nb][3] + s1);
            *(float2*)&outp[(size_t)g * D + col]       = v0;
            *(float2*)&outp[(size_t)(g + 8) * D + col] = v1;
        }
        __syncthreads();   // all warps done with sX/sS before next stage
    }
}

extern "C" void kernel_launch(void* const* d_in, const int* in_sizes, int n_in,
                              void* d_out, int out_size) {
    const float* x    = (const float*)d_in[0];
    const float* w1   = (const float*)d_in[1];
    const float* w2   = (const float*)d_in[2];
    const float* bias = (const float*)d_in[3];
    float* out = (float*)d_out;

    cudaFuncSetAttribute(gemm_kernel, cudaFuncAttributeMaxDynamicSharedMemorySize,
                         SMEM_BYTES);

    reduce_kernel<<<N_TILES, 256>>>(x);
    svec_kernel<<<B_DIM, 128>>>(w2, bias);
    gemm_kernel<<<GEMM_CTAS, GEMM_THREADS, SMEM_BYTES>>>(x, w1, out);
}